// round 1
// baseline (speedup 1.0000x reference)
#include <cuda_runtime.h>
#include <cstdint>
#include <cstddef>

#define NN 100000
#define EE 800000

// ---------------- scratch (static __device__ globals; no allocation) ----------------
__device__ float d_P[NN * 64];
__device__ float d_H1[(size_t)EE * 64];
__device__ float d_AGG[NN * 64];
__device__ float d_CB[NN * 96];
__device__ float d_T1[NN * 96];
__device__ float d_T2[NN * 96];
__device__ int   d_dgo[NN];
__device__ int   d_dgi[NN];
__device__ float d_stats[1152];
__device__ float d_W1f[64 * 64], d_c1f[64];
__device__ float d_W2f[64 * 64], d_c2f[64];
__device__ float d_W3f[64 * 64], d_c3f[64];
__device__ float d_V1f[96 * 96], d_d1f[96];
__device__ float d_V2f[96 * 96], d_d2f[96];
__device__ float d_V3f[96 * 32], d_d3f[32];

__device__ __forceinline__ float lrelu(float v) { return v > 0.f ? v : 0.1f * v; }

// ---------------- zero scratch ----------------
__global__ void zero_k(float* agg, int* dgo, int* dgi, float* st) {
    int i = blockIdx.x * blockDim.x + threadIdx.x;
    int stride = gridDim.x * blockDim.x;
    for (int j = i; j < NN * 64; j += stride) agg[j] = 0.f;
    for (int j = i; j < NN; j += stride) { dgo[j] = 0; dgi[j] = 0; }
    for (int j = i; j < 1152; j += stride) st[j] = 0.f;
}

// ---------------- degree counts ----------------
__global__ void deg_k(const int* __restrict__ ei, int* dgo, int* dgi) {
    int i = blockIdx.x * blockDim.x + threadIdx.x;
    int stride = gridDim.x * blockDim.x;
    for (int e = i; e < EE; e += stride) {
        atomicAdd(&dgo[ei[e]], 1);
        atomicAdd(&dgi[ei[EE + e]], 1);
    }
}

// ---------------- 32-wide column stats ----------------
// MODE 0: plain stats of A (nrows x 32)
// MODE 1: degree-weighted stats (stats of gathered x over edges)
// MODE 2: plain stats of x + copy into CB[:, 0:32] (row stride 96)
template <int MODE>
__global__ void colstats_k(const float* __restrict__ A, int nrows,
                           const int* __restrict__ w, float* __restrict__ cb,
                           float* __restrict__ sum, float* __restrict__ sq) {
    int tid = threadIdx.x;
    int c = tid & 31;
    int i = blockIdx.x * blockDim.x + tid;
    int stride = gridDim.x * blockDim.x;  // multiple of 32 -> each thread fixed column
    float s = 0.f, q = 0.f;
    int tot = nrows * 32;
    for (int j = i; j < tot; j += stride) {
        float v = A[j];
        if (MODE == 1) {
            float wf = (float)w[j >> 5];
            s += wf * v; q += wf * v * v;
        } else {
            s += v; q += v * v;
            if (MODE == 2) cb[(j >> 5) * 96 + (j & 31)] = v;
        }
    }
    __shared__ float red[256];
    red[tid] = s;
    __syncthreads();
    if (tid < 32) {
        float a = 0.f;
#pragma unroll
        for (int g = 0; g < 8; g++) a += red[tid + 32 * g];
        atomicAdd(&sum[c], a);
    }
    __syncthreads();
    red[tid] = q;
    __syncthreads();
    if (tid < 32) {
        float a = 0.f;
#pragma unroll
        for (int g = 0; g < 8; g++) a += red[tid + 32 * g];
        atomicAdd(&sq[c], a);
    }
}

// ---------------- fold BN into the next Linear ----------------
// s = g*rsqrt(var+eps); t = b - mean*s;  Wf = diag(s)W;  cf = t@W + c
__global__ void fold_k(int K, int NC,
                       const float* __restrict__ g, const float* __restrict__ b,
                       const float* __restrict__ W, const float* __restrict__ c,
                       const float* __restrict__ ssum, const float* __restrict__ ssq,
                       float inv_cnt, float* __restrict__ Wf, float* __restrict__ cf) {
    __shared__ float s[96], t[96];
    int tid = threadIdx.x;
    if (tid < K) {
        float m = ssum[tid] * inv_cnt;
        float v = ssq[tid] * inv_cnt - m * m;
        float sc = g[tid] * rsqrtf(v + 1e-5f);
        s[tid] = sc;
        t[tid] = b[tid] - m * sc;
    }
    __syncthreads();
    for (int j = tid; j < NC; j += blockDim.x) {
        float acc = c[j];
        for (int k = 0; k < K; k++) {
            float w = W[k * NC + j];
            Wf[k * NC + j] = s[k] * w;
            acc += t[k] * w;
        }
        cf[j] = acc;
    }
}

// ---------------- generic fused GEMM ----------------
// out[M,NC] = act(A[M,K] @ W[K,NC] + bias (+ gather P[gidx]) ), opt stats, opt scatter
template <int K, int NC, int CPT, int RPT, int TPB,
          bool RELU, bool STATS, bool GATHERP, bool SCATTER, bool DEGBIAS>
__global__ void __launch_bounds__(TPB)
gemm_k(const float* __restrict__ A, int lda, int M,
       const float* __restrict__ W, const float* __restrict__ bias,
       float* __restrict__ out, int ldo, int ocol,
       const float* __restrict__ Pg, const int* __restrict__ gidx,
       const int* __restrict__ degb,
       float* __restrict__ ssum, float* __restrict__ ssq) {
    constexpr int TX = NC / CPT;
    constexpr int TY = TPB / TX;
    constexpr int ROWS = TY * RPT;
    constexpr int KP = K + 4;
    static_assert(TPB % TX == 0, "bad cfg");
    static_assert(!SCATTER || NC == 64, "scatter needs NC=64");
    static_assert(!GATHERP || NC == 64, "gather needs NC=64");
    static_assert(CPT % 4 == 0, "CPT mult of 4");

    extern __shared__ float sm[];
    float* As = sm;                 // ROWS*KP  (reused as scatter staging, stride NC<=KP)
    float* Ws = sm + ROWS * KP;     // K*NC
    float* red = Ws + K * NC;       // TY*NC

    const int tid = threadIdx.x;
    const int row0 = blockIdx.x * ROWS;

    for (int i = tid; i < K * NC; i += TPB) Ws[i] = W[i];
    for (int i = tid; i < ROWS * K; i += TPB) {
        int r = i / K, k = i - r * K;
        int g = row0 + r;
        As[r * KP + k] = (g < M) ? A[(size_t)g * lda + k] : 0.f;
    }
    __syncthreads();

    const int tx = tid % TX, ty = tid / TX;
    const int c0 = tx * CPT;

    float acc[RPT][CPT];
#pragma unroll
    for (int i = 0; i < RPT; i++)
#pragma unroll
        for (int j = 0; j < CPT; j++) acc[i][j] = 0.f;

#pragma unroll
    for (int k = 0; k < K; k += 4) {
        float4 a[RPT];
#pragma unroll
        for (int i = 0; i < RPT; i++)
            a[i] = *reinterpret_cast<const float4*>(&As[(ty + TY * i) * KP + k]);
#pragma unroll
        for (int kk = 0; kk < 4; kk++) {
            float wv[CPT];
#pragma unroll
            for (int j = 0; j < CPT; j += 4) {
                float4 t4 = *reinterpret_cast<const float4*>(&Ws[(k + kk) * NC + c0 + j]);
                wv[j] = t4.x; wv[j + 1] = t4.y; wv[j + 2] = t4.z; wv[j + 3] = t4.w;
            }
#pragma unroll
            for (int i = 0; i < RPT; i++) {
                float av = (kk == 0) ? a[i].x : (kk == 1) ? a[i].y : (kk == 2) ? a[i].z : a[i].w;
#pragma unroll
                for (int j = 0; j < CPT; j++)
                    acc[i][j] = fmaf(av, wv[j], acc[i][j]);
            }
        }
    }

    if (SCATTER) __syncthreads();   // everyone done reading As before staging reuse

    float bs[CPT];
#pragma unroll
    for (int j = 0; j < CPT; j++) bs[j] = bias ? bias[c0 + j] : 0.f;

    float cs[CPT], cq[CPT];
#pragma unroll
    for (int j = 0; j < CPT; j++) { cs[j] = 0.f; cq[j] = 0.f; }

#pragma unroll
    for (int i = 0; i < RPT; i++) {
        int r = ty + TY * i;
        int g = row0 + r;
        bool valid = (g < M);
        float pv[CPT];
#pragma unroll
        for (int j = 0; j < CPT; j++) pv[j] = 0.f;
        if (GATHERP && valid) {
            int src = gidx[g];
            const float* pr = Pg + (size_t)src * 64 + c0;
#pragma unroll
            for (int j = 0; j < CPT; j += 4) {
                float4 t4 = *reinterpret_cast<const float4*>(pr + j);
                pv[j] = t4.x; pv[j + 1] = t4.y; pv[j + 2] = t4.z; pv[j + 3] = t4.w;
            }
        }
        float db = 1.f;
        if (DEGBIAS) db = valid ? (float)degb[g] : 0.f;
        float v[CPT];
#pragma unroll
        for (int j = 0; j < CPT; j++) {
            float t = acc[i][j] + db * bs[j] + pv[j];
            if (RELU) t = lrelu(t);
            v[j] = t;
        }
        if (STATS && valid) {
#pragma unroll
            for (int j = 0; j < CPT; j++) { cs[j] += v[j]; cq[j] += v[j] * v[j]; }
        }
        if (SCATTER) {
#pragma unroll
            for (int j = 0; j < CPT; j++) As[r * NC + c0 + j] = v[j];
        } else if (valid) {
            float* op = out + (size_t)g * ldo + ocol + c0;
#pragma unroll
            for (int j = 0; j < CPT; j += 4)
                *reinterpret_cast<float4*>(op + j) = make_float4(v[j], v[j + 1], v[j + 2], v[j + 3]);
        }
    }

    if (SCATTER) {
        __syncthreads();            // staging complete
        int wid = tid >> 5, lane = tid & 31;
        for (int r = wid; r < ROWS; r += TPB / 32) {
            int g = row0 + r;
            if (g < M) {
                int dst = gidx[g];
                float* ap = out + (size_t)dst * 64;
                atomicAdd(ap + lane,      As[r * 64 + lane]);
                atomicAdd(ap + 32 + lane, As[r * 64 + 32 + lane]);
            }
        }
    }

    if (STATS) {
        __syncthreads();
#pragma unroll
        for (int j = 0; j < CPT; j++) red[ty * NC + c0 + j] = cs[j];
        __syncthreads();
        for (int c = tid; c < NC; c += TPB) {
            float s = 0.f;
#pragma unroll
            for (int gy = 0; gy < TY; gy++) s += red[gy * NC + c];
            atomicAdd(&ssum[c], s);
        }
        __syncthreads();
#pragma unroll
        for (int j = 0; j < CPT; j++) red[ty * NC + c0 + j] = cq[j];
        __syncthreads();
        for (int c = tid; c < NC; c += TPB) {
            float s = 0.f;
#pragma unroll
            for (int gy = 0; gy < TY; gy++) s += red[gy * NC + c];
            atomicAdd(&ssq[c], s);
        }
    }
}

// ---------------- host ----------------
#define SYM(ptr, arr) do { void* _p = nullptr; cudaGetSymbolAddress(&_p, arr); ptr = (decltype(ptr))_p; } while (0)

extern "C" void kernel_launch(void* const* d_in, const int* in_sizes, int n_in,
                              void* d_out, int out_size) {
    const float* x  = (const float*)d_in[0];
    const int*   ei = (const int*)d_in[1];
    const float* ea = (const float*)d_in[2];
    // d_in[3]=u, d_in[4]=batch: unused by the reference computation
    const float* m1_g1 = (const float*)d_in[5],  *m1_b1 = (const float*)d_in[6];
    const float* m1_w1 = (const float*)d_in[7],  *m1_c1 = (const float*)d_in[8];
    const float* m1_g2 = (const float*)d_in[9],  *m1_b2 = (const float*)d_in[10];
    const float* m1_w2 = (const float*)d_in[11], *m1_c2 = (const float*)d_in[12];
    const float* m1_g3 = (const float*)d_in[13], *m1_b3 = (const float*)d_in[14];
    const float* m1_w3 = (const float*)d_in[15], *m1_c3 = (const float*)d_in[16];
    const float* m2_g1 = (const float*)d_in[17], *m2_b1 = (const float*)d_in[18];
    const float* m2_w1 = (const float*)d_in[19], *m2_c1 = (const float*)d_in[20];
    const float* m2_g2 = (const float*)d_in[21], *m2_b2 = (const float*)d_in[22];
    const float* m2_w2 = (const float*)d_in[23], *m2_c2 = (const float*)d_in[24];
    const float* m2_g3 = (const float*)d_in[25], *m2_b3 = (const float*)d_in[26];
    const float* m2_w3 = (const float*)d_in[27], *m2_c3 = (const float*)d_in[28];

    float *P, *H1, *AGG, *CB, *T1, *T2, *ST;
    int *dgo, *dgi;
    float *W1f, *c1f, *W2f, *c2f, *W3f, *c3f, *V1f, *d1f, *V2f, *d2f, *V3f, *d3f;
    SYM(P, d_P); SYM(H1, d_H1); SYM(AGG, d_AGG); SYM(CB, d_CB);
    SYM(T1, d_T1); SYM(T2, d_T2); SYM(ST, d_stats);
    SYM(dgo, d_dgo); SYM(dgi, d_dgi);
    SYM(W1f, d_W1f); SYM(c1f, d_c1f);
    SYM(W2f, d_W2f); SYM(c2f, d_c2f);
    SYM(W3f, d_W3f); SYM(c3f, d_c3f);
    SYM(V1f, d_V1f); SYM(d1f, d_d1f);
    SYM(V2f, d_V2f); SYM(d2f, d_d2f);
    SYM(V3f, d_V3f); SYM(d3f, d_d3f);

    float *S0S = ST + 0,   *S0Q = ST + 96;
    float *S2S = ST + 192, *S2Q = ST + 288;
    float *S3S = ST + 384, *S3Q = ST + 480;
    float *B1S = ST + 576, *B1Q = ST + 672;
    float *B2S = ST + 768, *B2Q = ST + 864;
    float *B3S = ST + 960, *B3Q = ST + 1056;

    // smem bytes: (ROWS*(K+4) + K*NC + TY*NC) * 4
    constexpr int smemP   = (64 * 36  + 32 * 64 + 16 * 64) * 4;   // 21504
    constexpr int smemE1  = (256 * 36 + 32 * 64 + 32 * 64) * 4;   // 53248
    constexpr int smemE2  = (256 * 68 + 64 * 64 + 32 * 64) * 4;   // 94208
    constexpr int smemL3  = (64 * 68  + 64 * 64 + 16 * 64) * 4;   // 37888
    constexpr int smemM2  = (64 * 100 + 96 * 96 + 8 * 96) * 4;    // 65536
    constexpr int smemOUT = (64 * 100 + 96 * 32 + 32 * 32) * 4;   // 41984

    auto kP   = gemm_k<32, 64, 4, 4, 256, false, false, false, false, false>;
    auto kE1  = gemm_k<32, 64, 8, 8, 256, true,  true,  true,  false, false>;
    auto kE2  = gemm_k<64, 64, 8, 8, 256, true,  true,  false, true,  false>;
    auto kL3  = gemm_k<64, 64, 4, 4, 256, false, true,  false, false, true>;
    auto kM2  = gemm_k<96, 96, 4, 8, 192, true,  true,  false, false, false>;
    auto kOUT = gemm_k<96, 32, 4, 2, 256, false, false, false, false, false>;

    cudaFuncSetAttribute(kE1, cudaFuncAttributeMaxDynamicSharedMemorySize, smemE1);
    cudaFuncSetAttribute(kE2, cudaFuncAttributeMaxDynamicSharedMemorySize, smemE2);
    cudaFuncSetAttribute(kM2, cudaFuncAttributeMaxDynamicSharedMemorySize, smemM2);

    const float invE = 1.f / (float)EE;
    const float invN = 1.f / (float)NN;

    zero_k<<<2048, 256>>>(AGG, dgo, dgi, ST);
    deg_k<<<512, 256>>>(ei, dgo, dgi);

    // BN1 stats: cols 32..63 directly from edge_attr; cols 0..31 degree-weighted from x
    colstats_k<0><<<512, 256>>>(ea, EE, nullptr, nullptr, S0S + 32, S0Q + 32);
    colstats_k<1><<<256, 256>>>(x, NN, dgo, nullptr, S0S, S0Q);
    // also: copy x into CB[:,0:32] and take its plain stats for mlp2 BN1
    colstats_k<2><<<256, 256>>>(x, NN, nullptr, CB, B1S, B1Q);

    // fold BN1 -> W1f, c1f
    fold_k<<<1, 128>>>(64, 64, m1_g1, m1_b1, m1_w1, m1_c1, S0S, S0Q, invE, W1f, c1f);

    // P = x @ W1f[0:32]   (per-node precompute of the gathered half)
    kP<<<(NN + 63) / 64, 256, smemP>>>(x, 32, NN, W1f, nullptr, P, 64, 0,
                                       nullptr, nullptr, nullptr, nullptr, nullptr);

    // H1 = lrelu(P[row] + ea @ W1f[32:64] + c1f), accumulate BN2 stats
    kE1<<<EE / 256, 256, smemE1>>>(ea, 32, EE, W1f + 32 * 64, c1f, H1, 64, 0,
                                   P, ei, nullptr, S2S, S2Q);

    fold_k<<<1, 128>>>(64, 64, m1_g2, m1_b2, m1_w2, m1_c2, S2S, S2Q, invE, W2f, c2f);

    // h2 = lrelu(H1 @ W2f + c2f); BN3 stats; scatter-add into AGG[col]
    kE2<<<EE / 256, 256, smemE2>>>(H1, 64, EE, W2f, c2f, AGG, 64, 0,
                                   nullptr, ei + EE, nullptr, S3S, S3Q);

    fold_k<<<1, 128>>>(64, 64, m1_g3, m1_b3, m1_w3, m1_c3, S3S, S3Q, invE, W3f, c3f);

    // CB[:,32:96] = AGG @ W3f + deg_in * c3f   (segsum pushed through the linear layer)
    kL3<<<(NN + 63) / 64, 256, smemL3>>>(AGG, 64, NN, W3f, c3f, CB, 96, 32,
                                         nullptr, nullptr, dgi, B1S + 32, B1Q + 32);

    fold_k<<<1, 128>>>(96, 96, m2_g1, m2_b1, m2_w1, m2_c1, B1S, B1Q, invN, V1f, d1f);

    kM2<<<(NN + 63) / 64, 192, smemM2>>>(CB, 96, NN, V1f, d1f, T1, 96, 0,
                                         nullptr, nullptr, nullptr, B2S, B2Q);

    fold_k<<<1, 128>>>(96, 96, m2_g2, m2_b2, m2_w2, m2_c2, B2S, B2Q, invN, V2f, d2f);

    kM2<<<(NN + 63) / 64, 192, smemM2>>>(T1, 96, NN, V2f, d2f, T2, 96, 0,
                                         nullptr, nullptr, nullptr, B3S, B3Q);

    fold_k<<<1, 128>>>(96, 32, m2_g3, m2_b3, m2_w3, m2_c3, B3S, B3Q, invN, V3f, d3f);

    kOUT<<<(NN + 63) / 64, 256, smemOUT>>>(T2, 96, NN, V3f, d3f, (float*)d_out, 32, 0,
                                           nullptr, nullptr, nullptr, nullptr, nullptr);
}

// round 3
// speedup vs baseline: 1.2116x; 1.2116x over previous
#include <cuda_runtime.h>
#include <cuda_bf16.h>
#include <cstdint>
#include <cstddef>

#define NN 100000
#define EE 800000

// ---------------- scratch (static __device__ globals; no allocation) ----------------
__device__ float d_P[NN * 64];
__device__ __nv_bfloat16 d_Hh[(size_t)EE * 64];
__device__ __nv_bfloat16 d_Hl[(size_t)EE * 64];
__device__ float d_AGG[NN * 64];
__device__ float d_CB[NN * 96];
__device__ float d_T1[NN * 96];
__device__ float d_T2[NN * 96];
__device__ int   d_dgo[NN];
__device__ int   d_dgi[NN];
__device__ float d_stats[1152];
__device__ float d_W1f[64 * 64], d_c1f[64];
__device__ float d_W2f[64 * 64], d_c2f[64];
__device__ float d_W3f[64 * 64], d_c3f[64];
__device__ float d_V1f[96 * 96], d_d1f[96];
__device__ float d_V2f[96 * 96], d_d2f[96];
__device__ float d_V3f[96 * 32], d_d3f[32];
// pre-split transposed weight blobs: [Wh: NC*(K+8) bf16][Wl: NC*(K+8) bf16]
__device__ uint4 d_Bp[640];     // K=32, NC=64
__device__ uint4 d_Be1[640];    // K=32, NC=64
__device__ uint4 d_Be2[1152];   // K=64, NC=64
__device__ uint4 d_Bl3[1152];   // K=64, NC=64
__device__ uint4 d_Bm1[2496];   // K=96, NC=96
__device__ uint4 d_Bm2[2496];   // K=96, NC=96
__device__ uint4 d_Bo[832];     // K=96, NC=32

__device__ __forceinline__ float lrelu(float v) { return v > 0.f ? v : 0.1f * v; }

// ---------------- zero scratch ----------------
__global__ void zero_k(float* agg, int* dgo, int* dgi, float* st) {
    int i = blockIdx.x * blockDim.x + threadIdx.x;
    int stride = gridDim.x * blockDim.x;
    for (int j = i; j < NN * 64; j += stride) agg[j] = 0.f;
    for (int j = i; j < NN; j += stride) { dgo[j] = 0; dgi[j] = 0; }
    for (int j = i; j < 1152; j += stride) st[j] = 0.f;
}

// ---------------- degree counts ----------------
__global__ void deg_k(const int* __restrict__ ei, int* dgo, int* dgi) {
    int i = blockIdx.x * blockDim.x + threadIdx.x;
    int stride = gridDim.x * blockDim.x;
    for (int e = i; e < EE; e += stride) {
        atomicAdd(&dgo[ei[e]], 1);
        atomicAdd(&dgi[ei[EE + e]], 1);
    }
}

// ---------------- 32-wide column stats ----------------
// MODE 0: plain stats of A (nrows x 32)
// MODE 1: degree-weighted stats (stats of gathered x over edges)
// MODE 2: plain stats of x + copy into CB[:, 0:32] (row stride 96)
template <int MODE>
__global__ void colstats_k(const float* __restrict__ A, int nrows,
                           const int* __restrict__ w, float* __restrict__ cb,
                           float* __restrict__ sum, float* __restrict__ sq) {
    int tid = threadIdx.x;
    int c = tid & 31;
    int i = blockIdx.x * blockDim.x + tid;
    int stride = gridDim.x * blockDim.x;
    float s = 0.f, q = 0.f;
    int tot = nrows * 32;
    for (int j = i; j < tot; j += stride) {
        float v = A[j];
        if (MODE == 1) {
            float wf = (float)w[j >> 5];
            s += wf * v; q += wf * v * v;
        } else {
            s += v; q += v * v;
            if (MODE == 2) cb[(j >> 5) * 96 + (j & 31)] = v;
        }
    }
    __shared__ float red[256];
    red[tid] = s;
    __syncthreads();
    if (tid < 32) {
        float a = 0.f;
#pragma unroll
        for (int g = 0; g < 8; g++) a += red[tid + 32 * g];
        atomicAdd(&sum[c], a);
    }
    __syncthreads();
    red[tid] = q;
    __syncthreads();
    if (tid < 32) {
        float a = 0.f;
#pragma unroll
        for (int g = 0; g < 8; g++) a += red[tid + 32 * g];
        atomicAdd(&sq[c], a);
    }
}

// ---------------- fold BN into the next Linear ----------------
__global__ void fold_k(int K, int NC,
                       const float* __restrict__ g, const float* __restrict__ b,
                       const float* __restrict__ W, const float* __restrict__ c,
                       const float* __restrict__ ssum, const float* __restrict__ ssq,
                       float inv_cnt, float* __restrict__ Wf, float* __restrict__ cf) {
    __shared__ float s[96], t[96];
    int tid = threadIdx.x;
    if (tid < K) {
        float m = ssum[tid] * inv_cnt;
        float v = ssq[tid] * inv_cnt - m * m;
        float sc = g[tid] * rsqrtf(v + 1e-5f);
        s[tid] = sc;
        t[tid] = b[tid] - m * sc;
    }
    __syncthreads();
    for (int j = tid; j < NC; j += blockDim.x) {
        float acc = c[j];
        for (int k = 0; k < K; k++) {
            float w = W[k * NC + j];
            Wf[k * NC + j] = s[k] * w;
            acc += t[k] * w;
        }
        cf[j] = acc;
    }
}

// ---------------- weight -> transposed, padded, bf16 hi/lo blob ----------------
// W [K, NC] row-major -> WT [NC][K+8], hi image then lo image
__global__ void bprep_k(const float* __restrict__ W, int K, int NC,
                        __nv_bfloat16* __restrict__ blob) {
    int i = blockIdx.x * blockDim.x + threadIdx.x;
    if (i >= K * NC) return;
    int k = i / NC, n = i - k * NC;
    int KP = K + 8;
    float w = W[i];
    __nv_bfloat16 h = __float2bfloat16(w);
    __nv_bfloat16 l = __float2bfloat16(w - __bfloat162float(h));
    blob[n * KP + k] = h;
    blob[NC * KP + n * KP + k] = l;
}

// ---------------- mma.sync fused GEMM: out[M,NC] = epi(A[M,K] @ W[K,NC]) ----------------
// bf16 3-term split: D = Ah*Wh + Ah*Wl + Al*Wh. 128 rows/block, 4 warps.
template <int K, int NC, bool RELU, bool STATS, bool GATHERP, bool SCATTER,
          bool DEGBIAS, bool ASPLIT, bool OUTSPLIT>
__global__ void __launch_bounds__(128)
tgemm_k(const float* __restrict__ A, int lda, int M,
        const __nv_bfloat16* __restrict__ Ahg, const __nv_bfloat16* __restrict__ Alg,
        const uint4* __restrict__ Bblob,
        const float* __restrict__ bias,
        float* __restrict__ out, int ldo, int ocol,
        __nv_bfloat16* __restrict__ Oh, __nv_bfloat16* __restrict__ Ol,
        const float* __restrict__ Pg, const int* __restrict__ gidx,
        const int* __restrict__ degb,
        float* __restrict__ ssum, float* __restrict__ ssq) {
    constexpr int KP = K + 8;                    // padded row (16B extra) -> conflict-free frags
    constexpr int SW = NC + 2;                   // staging row stride (floats)
    constexpr int MAXW = (KP > SW) ? KP : SW;
    constexpr int S1 = 128 * MAXW * 4;           // bytes: A(hi+lo) region, reused as staging
    constexpr int NT = NC / 8;
    constexpr int KS = K / 16;

    extern __shared__ unsigned char sm[];
    __nv_bfloat16* smAh = (__nv_bfloat16*)sm;
    __nv_bfloat16* smAl = smAh + 128 * KP;
    __nv_bfloat16* smWh = (__nv_bfloat16*)(sm + S1);
    __nv_bfloat16* smWl = smWh + NC * KP;
    float* stg = (float*)sm;

    const int tid = threadIdx.x;
    const int lane = tid & 31, wrp = tid >> 5;
    const int g8 = lane >> 2, tg = lane & 3;
    const int row0 = blockIdx.x * 128;

    // ---- W copy (blob layout == smem layout) ----
    {
        uint4* wd = (uint4*)smWh;
        for (int i = tid; i < NC * KP / 4; i += 128) wd[i] = Bblob[i];
    }
    // ---- A fill (+ fp32->bf16 hi/lo split unless pre-split) ----
    {
        constexpr int KH = K / 2;
        for (int idx = tid; idx < 128 * KH; idx += 128) {
            int row = idx / KH;
            int k = (idx - row * KH) * 2;
            int g = row0 + row;
            uint32_t hw = 0, lw = 0;
            if (ASPLIT) {
                if (g < M) {
                    hw = *(const uint32_t*)(Ahg + (size_t)g * K + k);
                    lw = *(const uint32_t*)(Alg + (size_t)g * K + k);
                }
            } else {
                float ax = 0.f, ay = 0.f;
                if (g < M) {
                    float2 t = *(const float2*)(A + (size_t)g * lda + k);
                    ax = t.x; ay = t.y;
                }
                __nv_bfloat16 hx = __float2bfloat16(ax), hy = __float2bfloat16(ay);
                __nv_bfloat16 lx = __float2bfloat16(ax - __bfloat162float(hx));
                __nv_bfloat16 ly = __float2bfloat16(ay - __bfloat162float(hy));
                hw = (uint32_t)__bfloat16_as_ushort(hx) |
                     ((uint32_t)__bfloat16_as_ushort(hy) << 16);
                lw = (uint32_t)__bfloat16_as_ushort(lx) |
                     ((uint32_t)__bfloat16_as_ushort(ly) << 16);
            }
            *(uint32_t*)(smAh + row * KP + k) = hw;
            *(uint32_t*)(smAl + row * KP + k) = lw;
        }
    }
    __syncthreads();

    // ---- mma compute: acc[mt][nt][4] ----
    float acc[2][NT][4];
#pragma unroll
    for (int mt = 0; mt < 2; mt++)
#pragma unroll
        for (int nt = 0; nt < NT; nt++)
#pragma unroll
            for (int j = 0; j < 4; j++) acc[mt][nt][j] = 0.f;

    const __nv_bfloat16* APTR[3] = {smAh, smAh, smAl};
    const __nv_bfloat16* WPTR[3] = {smWh, smWl, smWh};
#pragma unroll
    for (int t = 0; t < 3; t++) {
        const __nv_bfloat16* Ab = APTR[t];
        const __nv_bfloat16* Wb = WPTR[t];
#pragma unroll
        for (int ks = 0; ks < KS; ks++) {
            uint32_t a[2][4];
#pragma unroll
            for (int mt = 0; mt < 2; mt++) {
                int row = wrp * 32 + mt * 16 + g8;
                const uint32_t* p  = (const uint32_t*)(Ab + row * KP + ks * 16 + tg * 2);
                const uint32_t* p8 = (const uint32_t*)(Ab + (row + 8) * KP + ks * 16 + tg * 2);
                a[mt][0] = p[0];  a[mt][1] = p8[0];
                a[mt][2] = p[4];  a[mt][3] = p8[4];
            }
#pragma unroll
            for (int nt = 0; nt < NT; nt++) {
                const uint32_t* q = (const uint32_t*)(Wb + (nt * 8 + g8) * KP + ks * 16 + tg * 2);
                uint32_t b0 = q[0], b1 = q[4];
#pragma unroll
                for (int mt = 0; mt < 2; mt++) {
                    asm volatile(
                        "mma.sync.aligned.m16n8k16.row.col.f32.bf16.bf16.f32 "
                        "{%0,%1,%2,%3}, {%4,%5,%6,%7}, {%8,%9}, {%0,%1,%2,%3};"
                        : "+f"(acc[mt][nt][0]), "+f"(acc[mt][nt][1]),
                          "+f"(acc[mt][nt][2]), "+f"(acc[mt][nt][3])
                        : "r"(a[mt][0]), "r"(a[mt][1]), "r"(a[mt][2]), "r"(a[mt][3]),
                          "r"(b0), "r"(b1));
                }
            }
        }
    }
    __syncthreads();   // A reads done; staging may overwrite

    // ---- fragments -> staging ----
#pragma unroll
    for (int mt = 0; mt < 2; mt++) {
        int r0 = wrp * 32 + mt * 16 + g8;
#pragma unroll
        for (int nt = 0; nt < NT; nt++) {
            int c = nt * 8 + tg * 2;
            *(float2*)&stg[r0 * SW + c]       = make_float2(acc[mt][nt][0], acc[mt][nt][1]);
            *(float2*)&stg[(r0 + 8) * SW + c] = make_float2(acc[mt][nt][2], acc[mt][nt][3]);
        }
    }
    __syncthreads();

    // ---- per-row epilogue: thread tid owns row row0+tid ----
    const int g = row0 + tid;
    const bool valid = g < M;
    int other = 0;
    if ((SCATTER || GATHERP) && valid) other = gidx[g];
    float db = 1.f;
    if (DEGBIAS) db = valid ? (float)degb[g] : 0.f;

#pragma unroll
    for (int ch = 0; ch < NC; ch += 32) {
        float v[32];
#pragma unroll
        for (int c = 0; c < 32; c += 2) {
            float2 t = *(float2*)&stg[tid * SW + ch + c];
            v[c] = t.x; v[c + 1] = t.y;
        }
        if (GATHERP) {
#pragma unroll
            for (int j = 0; j < 32; j += 4) {
                float4 t = valid ? *(const float4*)(Pg + (size_t)other * 64 + ch + j)
                                 : make_float4(0.f, 0.f, 0.f, 0.f);
                v[j] += t.x; v[j + 1] += t.y; v[j + 2] += t.z; v[j + 3] += t.w;
            }
        }
#pragma unroll
        for (int j = 0; j < 32; j++) {
            float b = bias ? __ldg(bias + ch + j) : 0.f;
            float t = v[j] + db * b;
            if (RELU) t = lrelu(t);
            v[j] = t;
        }
        if (!SCATTER && !OUTSPLIT) {
            if (valid) {
#pragma unroll
                for (int j = 0; j < 32; j += 4)
                    *(float4*)(out + (size_t)g * ldo + ocol + ch + j) =
                        make_float4(v[j], v[j + 1], v[j + 2], v[j + 3]);
            }
        }
        if (STATS || SCATTER || OUTSPLIT) {
#pragma unroll
            for (int c = 0; c < 32; c += 2)
                *(float2*)&stg[tid * SW + ch + c] =
                    make_float2(valid ? v[c] : 0.f, valid ? v[c + 1] : 0.f);
        }
    }

    if (STATS || SCATTER || OUTSPLIT) __syncthreads();

    if (SCATTER) {
        // warp-per-row coalesced atomics (NC == 64)
        for (int r = wrp; r < 128; r += 4) {
            int gr = row0 + r;
            if (gr < M) {
                int dst = gidx[gr];
                float* ap = out + (size_t)dst * 64;
                atomicAdd(ap + lane,      stg[r * SW + lane]);
                atomicAdd(ap + 32 + lane, stg[r * SW + 32 + lane]);
            }
        }
    }

    if (OUTSPLIT) {
        // coalesced packed split write (NC == 64)
        for (int i = tid; i < 128 * 32; i += 128) {
            int r = i >> 5, c2 = i & 31;
            int gr = row0 + r;
            if (gr < M) {
                float a0 = stg[r * SW + 2 * c2], a1 = stg[r * SW + 2 * c2 + 1];
                __nv_bfloat16 h0 = __float2bfloat16(a0), h1 = __float2bfloat16(a1);
                __nv_bfloat16 l0 = __float2bfloat16(a0 - __bfloat162float(h0));
                __nv_bfloat16 l1 = __float2bfloat16(a1 - __bfloat162float(h1));
                uint32_t hw = (uint32_t)__bfloat16_as_ushort(h0) |
                              ((uint32_t)__bfloat16_as_ushort(h1) << 16);
                uint32_t lw = (uint32_t)__bfloat16_as_ushort(l0) |
                              ((uint32_t)__bfloat16_as_ushort(l1) << 16);
                ((uint32_t*)Oh)[(size_t)gr * 32 + c2] = hw;
                ((uint32_t*)Ol)[(size_t)gr * 32 + c2] = lw;
            }
        }
    }

    if (STATS) {
        if (tid < NC) {
            float s = 0.f, q = 0.f;
            for (int r = 0; r < 128; r++) {
                float t = stg[r * SW + tid];
                s += t; q += t * t;
            }
            atomicAdd(&ssum[tid], s);
            atomicAdd(&ssq[tid], q);
        }
    }
}

// ---------------- host ----------------
#define SYM(ptr, arr) do { void* _p = nullptr; cudaGetSymbolAddress(&_p, arr); ptr = (decltype(ptr))_p; } while (0)

static constexpr int smem_sz(int K, int NC) {
    int KP = K + 8, SW = NC + 2;
    int MAXW = KP > SW ? KP : SW;
    return 128 * MAXW * 4 + NC * KP * 4;
}

extern "C" void kernel_launch(void* const* d_in, const int* in_sizes, int n_in,
                              void* d_out, int out_size) {
    const float* x  = (const float*)d_in[0];
    const int*   ei = (const int*)d_in[1];
    const float* ea = (const float*)d_in[2];
    const float* m1_g1 = (const float*)d_in[5],  *m1_b1 = (const float*)d_in[6];
    const float* m1_w1 = (const float*)d_in[7],  *m1_c1 = (const float*)d_in[8];
    const float* m1_g2 = (const float*)d_in[9],  *m1_b2 = (const float*)d_in[10];
    const float* m1_w2 = (const float*)d_in[11], *m1_c2 = (const float*)d_in[12];
    const float* m1_g3 = (const float*)d_in[13], *m1_b3 = (const float*)d_in[14];
    const float* m1_w3 = (const float*)d_in[15], *m1_c3 = (const float*)d_in[16];
    const float* m2_g1 = (const float*)d_in[17], *m2_b1 = (const float*)d_in[18];
    const float* m2_w1 = (const float*)d_in[19], *m2_c1 = (const float*)d_in[20];
    const float* m2_g2 = (const float*)d_in[21], *m2_b2 = (const float*)d_in[22];
    const float* m2_w2 = (const float*)d_in[23], *m2_c2 = (const float*)d_in[24];
    const float* m2_g3 = (const float*)d_in[25], *m2_b3 = (const float*)d_in[26];
    const float* m2_w3 = (const float*)d_in[27], *m2_c3 = (const float*)d_in[28];

    float *P, *AGG, *CB, *T1, *T2, *ST;
    __nv_bfloat16 *Hh, *Hl;
    int *dgo, *dgi;
    float *W1f, *c1f, *W2f, *c2f, *W3f, *c3f, *V1f, *d1f, *V2f, *d2f, *V3f, *d3f;
    uint4 *Bp, *Be1, *Be2, *Bl3, *Bm1, *Bm2, *Bo;
    SYM(P, d_P); SYM(Hh, d_Hh); SYM(Hl, d_Hl); SYM(AGG, d_AGG); SYM(CB, d_CB);
    SYM(T1, d_T1); SYM(T2, d_T2); SYM(ST, d_stats);
    SYM(dgo, d_dgo); SYM(dgi, d_dgi);
    SYM(W1f, d_W1f); SYM(c1f, d_c1f);
    SYM(W2f, d_W2f); SYM(c2f, d_c2f);
    SYM(W3f, d_W3f); SYM(c3f, d_c3f);
    SYM(V1f, d_V1f); SYM(d1f, d_d1f);
    SYM(V2f, d_V2f); SYM(d2f, d_d2f);
    SYM(V3f, d_V3f); SYM(d3f, d_d3f);
    SYM(Bp, d_Bp); SYM(Be1, d_Be1); SYM(Be2, d_Be2); SYM(Bl3, d_Bl3);
    SYM(Bm1, d_Bm1); SYM(Bm2, d_Bm2); SYM(Bo, d_Bo);

    float *S0S = ST + 0,   *S0Q = ST + 96;
    float *S2S = ST + 192, *S2Q = ST + 288;
    float *S3S = ST + 384, *S3Q = ST + 480;
    float *B1S = ST + 576, *B1Q = ST + 672;
    float *B2S = ST + 768, *B2Q = ST + 864;
    float *B3S = ST + 960, *B3Q = ST + 1056;

    // <K,NC,RELU,STATS,GATHERP,SCATTER,DEGBIAS,ASPLIT,OUTSPLIT>
    auto kP  = tgemm_k<32, 64, false, false, false, false, false, false, false>;
    auto kE1 = tgemm_k<32, 64, true,  true,  true,  false, false, false, true >;
    auto kE2 = tgemm_k<64, 64, true,  true,  false, true,  false, true,  false>;
    auto kL3 = tgemm_k<64, 64, false, true,  false, false, true,  false, false>;
    auto kM2 = tgemm_k<96, 96, true,  true,  false, false, false, false, false>;
    auto kO  = tgemm_k<96, 32, false, false, false, false, false, false, false>;

    constexpr int smP  = smem_sz(32, 64);   // 44032
    constexpr int smE2 = smem_sz(64, 64);   // 55296
    constexpr int smM2 = smem_sz(96, 96);   // 93184
    constexpr int smO  = smem_sz(96, 32);   // 66560

    cudaFuncSetAttribute(kP,  cudaFuncAttributeMaxDynamicSharedMemorySize, smP);
    cudaFuncSetAttribute(kE1, cudaFuncAttributeMaxDynamicSharedMemorySize, smP);
    cudaFuncSetAttribute(kE2, cudaFuncAttributeMaxDynamicSharedMemorySize, smE2);
    cudaFuncSetAttribute(kL3, cudaFuncAttributeMaxDynamicSharedMemorySize, smE2);
    cudaFuncSetAttribute(kM2, cudaFuncAttributeMaxDynamicSharedMemorySize, smM2);
    cudaFuncSetAttribute(kO,  cudaFuncAttributeMaxDynamicSharedMemorySize, smO);

    const float invE = 1.f / (float)EE;
    const float invN = 1.f / (float)NN;
    const int EB = EE / 128;             // 6250
    const int NB = (NN + 127) / 128;     // 782

    zero_k<<<2048, 256>>>(AGG, dgo, dgi, ST);
    deg_k<<<512, 256>>>(ei, dgo, dgi);

    colstats_k<0><<<512, 256>>>(ea, EE, nullptr, nullptr, S0S + 32, S0Q + 32);
    colstats_k<1><<<256, 256>>>(x, NN, dgo, nullptr, S0S, S0Q);
    colstats_k<2><<<256, 256>>>(x, NN, nullptr, CB, B1S, B1Q);

    fold_k<<<1, 128>>>(64, 64, m1_g1, m1_b1, m1_w1, m1_c1, S0S, S0Q, invE, W1f, c1f);
    bprep_k<<<16, 128>>>(W1f, 32, 64, (__nv_bfloat16*)Bp);
    bprep_k<<<16, 128>>>(W1f + 32 * 64, 32, 64, (__nv_bfloat16*)Be1);

    // P = x @ W1f[0:32]
    kP<<<NB, 128, smP>>>(x, 32, NN, nullptr, nullptr, Bp, nullptr,
                         P, 64, 0, nullptr, nullptr, nullptr, nullptr, nullptr,
                         nullptr, nullptr);
    // H = lrelu(P[row] + ea @ W1f[32:64] + c1f) -> split bf16 (Hh,Hl); BN2 stats
    kE1<<<EB, 128, smP>>>(ea, 32, EE, nullptr, nullptr, Be1, c1f,
                          nullptr, 0, 0, Hh, Hl, P, ei, nullptr, S2S, S2Q);

    fold_k<<<1, 128>>>(64, 64, m1_g2, m1_b2, m1_w2, m1_c2, S2S, S2Q, invE, W2f, c2f);
    bprep_k<<<32, 128>>>(W2f, 64, 64, (__nv_bfloat16*)Be2);

    // h2 = lrelu(H @ W2f + c2f); BN3 stats; scatter-add into AGG[col]
    kE2<<<EB, 128, smE2>>>(nullptr, 0, EE, Hh, Hl, Be2, c2f,
                           AGG, 0, 0, nullptr, nullptr, nullptr, ei + EE, nullptr,
                           S3S, S3Q);

    fold_k<<<1, 128>>>(64, 64, m1_g3, m1_b3, m1_w3, m1_c3, S3S, S3Q, invE, W3f, c3f);
    bprep_k<<<32, 128>>>(W3f, 64, 64, (__nv_bfloat16*)Bl3);

    // CB[:,32:96] = AGG @ W3f + deg_in * c3f
    kL3<<<NB, 128, smE2>>>(AGG, 64, NN, nullptr, nullptr, Bl3, c3f,
                           CB, 96, 32, nullptr, nullptr, nullptr, nullptr, dgi,
                           B1S + 32, B1Q + 32);

    fold_k<<<1, 128>>>(96, 96, m2_g1, m2_b1, m2_w1, m2_c1, B1S, B1Q, invN, V1f, d1f);
    bprep_k<<<72, 128>>>(V1f, 96, 96, (__nv_bfloat16*)Bm1);

    kM2<<<NB, 128, smM2>>>(CB, 96, NN, nullptr, nullptr, Bm1, d1f,
                           T1, 96, 0, nullptr, nullptr, nullptr, nullptr, nullptr,
                           B2S, B2Q);

    fold_k<<<1, 128>>>(96, 96, m2_g2, m2_b2, m2_w2, m2_c2, B2S, B2Q, invN, V2f, d2f);
    bprep_k<<<72, 128>>>(V2f, 96, 96, (__nv_bfloat16*)Bm2);

    kM2<<<NB, 128, smM2>>>(T1, 96, NN, nullptr, nullptr, Bm2, d2f,
                           T2, 96, 0, nullptr, nullptr, nullptr, nullptr, nullptr,
                           B3S, B3Q);

    fold_k<<<1, 128>>>(96, 32, m2_g3, m2_b3, m2_w3, m2_c3, B3S, B3Q, invN, V3f, d3f);
    bprep_k<<<24, 128>>>(V3f, 96, 32, (__nv_bfloat16*)Bo);

    kO<<<NB, 128, smO>>>(T2, 96, NN, nullptr, nullptr, Bo, d3f,
                         (float*)d_out, 32, 0, nullptr, nullptr, nullptr, nullptr, nullptr,
                         nullptr, nullptr);
}